// round 16
// baseline (speedup 1.0000x reference)
#include <cuda_runtime.h>
#include <math.h>

#define BT 128
#define HWPX 16384
#define WF 65
#define NYK 8320

typedef unsigned long long u64;

__device__ float  d_z1[BT*16*HWPX];
__device__ float  d_ga[BT*16*HWPX];
__device__ float  d_gb[BT*16*HWPX];
__device__ float  d_Xt[BT*8*HWPX];
__device__ float2 d_S [1024*NYK];
__device__ float2 d_S2[1024*NYK];
__device__ float  d_omega[NYK*8];
__device__ float  d_scale[BT];

__device__ __forceinline__ float sg_(float z){ return 1.f/(1.f+__expf(-z)); }
__device__ __forceinline__ float silu_(float z){ return z*sg_(z); }
__device__ __forceinline__ float silup_(float z){ float s=sg_(z); return s+z*s*(1.f-s); }
__device__ __forceinline__ float2 cadd2(float2 a,float2 b){ return make_float2(a.x+b.x,a.y+b.y); }
__device__ __forceinline__ float2 csub2(float2 a,float2 b){ return make_float2(a.x-b.x,a.y-b.y); }
__device__ __forceinline__ float2 cmul2(float2 a,float2 b){ return make_float2(fmaf(a.x,b.x,-(a.y*b.y)),fmaf(a.x,b.y,a.y*b.x)); }
template<int S> __device__ __forceinline__ float2 rotmi(float2 a){ return (S>0)?make_float2(a.y,-a.x):make_float2(-a.y,a.x); }

template<int S> __device__ __forceinline__ void dft4(float2&x0,float2&x1,float2&x2,float2&x3){
    float2 t0=cadd2(x0,x2),t1=csub2(x0,x2),t2=cadd2(x1,x3),t3=csub2(x1,x3);
    x0=cadd2(t0,t2); x2=csub2(t0,t2); float2 r=rotmi<S>(t3); x1=cadd2(t1,r); x3=csub2(t1,r);
}
template<int S> __device__ __forceinline__ void dft8(float2 a[8]){
    float2 e0=a[0],e1=a[2],e2=a[4],e3=a[6],o0=a[1],o1=a[3],o2=a[5],o3=a[7];
    dft4<S>(e0,e1,e2,e3); dft4<S>(o0,o1,o2,o3);
    const float c8=0.70710678118654752f; float2 w1o,w3o;
    if(S>0){ w1o=make_float2(c8*(o1.x+o1.y),c8*(o1.y-o1.x)); w3o=make_float2(c8*(o3.y-o3.x),-c8*(o3.x+o3.y)); }
    else   { w1o=make_float2(c8*(o1.x-o1.y),c8*(o1.y+o1.x)); w3o=make_float2(-c8*(o3.x+o3.y),c8*(o3.x-o3.y)); }
    float2 w2o=rotmi<S>(o2);
    a[0]=cadd2(e0,o0); a[4]=csub2(e0,o0); a[1]=cadd2(e1,w1o); a[5]=csub2(e1,w1o);
    a[2]=cadd2(e2,w2o); a[6]=csub2(e2,w2o); a[3]=cadd2(e3,w3o); a[7]=csub2(e3,w3o);
}
template<int S> __device__ __forceinline__ void dft16(float2 b[16]){
    float2 e[8],o[8];
#pragma unroll
    for(int r=0;r<8;r++){ e[r]=b[2*r]; o[r]=b[2*r+1]; }
    dft8<S>(e); dft8<S>(o);
    const float CW[8]={1.f,0.92387953251128674f,0.70710678118654752f,0.38268343236508977f,0.f,-0.38268343236508977f,-0.70710678118654752f,-0.92387953251128674f};
    const float SW[8]={0.f,0.38268343236508977f,0.70710678118654752f,0.92387953251128674f,1.f,0.92387953251128674f,0.70710678118654752f,0.38268343236508977f};
#pragma unroll
    for(int m=0;m<8;m++){
        float2 w=make_float2(CW[m],(S>0)?-SW[m]:SW[m]);
        float2 wo=cmul2(o[m],w); b[m]=cadd2(e[m],wo); b[m+8]=csub2(e[m],wo);
    }
}
template<int S> __device__ __forceinline__ void fft128(float2 x[8],float2 out[16],int t,float2* wbuf,const float2* tw){
    dft8<S>(x);
#pragma unroll
    for(int k=0;k<8;k++){
        float2 v;
        if(k==0) v=x[0];
        else { float2 w=tw[t*k]; if(S<0) w.y=-w.y; v=cmul2(x[k],w); }
        wbuf[k*17+t]=v;
    }
    __syncthreads();
    if(t<8){
        float2 b[16];
#pragma unroll
        for(int m=0;m<16;m++) b[m]=wbuf[t*17+m];
        dft16<S>(b);
#pragma unroll
        for(int m=0;m<16;m++) out[m]=b[m];
    }
}
__device__ __forceinline__ void build_tw(float2* tw,int tid){
    if(tid<128){ float s,c; sincosf(-6.283185307179586477f*(float)tid/128.f,&s,&c); tw[tid]=make_float2(c,s); }
}

__device__ __forceinline__ u64 pack2(float v){
    u64 d; unsigned r=__float_as_uint(v);
    asm("mov.b64 %0,{%1,%2};" : "=l"(d) : "r"(r), "r"(r));
    return d;
}
__device__ __forceinline__ void fma2_(u64& a, u64 b, u64 c){
    asm("fma.rn.f32x2 %0,%1,%2,%0;" : "+l"(a) : "l"(b), "l"(c));
}
__device__ __forceinline__ void unpack2(u64 d, float& lo, float& hi){
    unsigned a,b; asm("mov.b64 {%0,%1},%2;" : "=r"(a), "=r"(b) : "l"(d));
    lo=__uint_as_float(a); hi=__uint_as_float(b);
}

// FFMA2 conv: weights [ci][tap][o] (o-pair = LDS.64), pixels duplicated into f32x2.
// ~43% fewer issued instructions than scalar; full fp32 precision.
// MODE 0: z1=conv1(x)+b1 | 1: s2*silu'(conv2(silu(z1))+b2) | 2: conv2T(ga)*silu'(z1) | 3: x+dt*conv1T(gb)
template<int CI,int CO,int MODE>
__global__ void __launch_bounds__(256) k_conv(const float* __restrict__ in,float* __restrict__ out,
        const float* __restrict__ w,const float* __restrict__ bias,
        const float* __restrict__ aux1,const float* __restrict__ aux2){
    extern __shared__ float sm[];
    float* sin_=sm;                    // CI*1296 (18x72 tiles)
    float* sw2 =sm+CI*1296;            // CI*9*CO, layout (ci*9+k)*CO+o
    float* sb  =sw2+CI*9*CO;
    float* s2s =sb+16;
    const int tid=threadIdx.x;
    const int tx=tid&63, ty=tid>>6;
    const int img=blockIdx.z;
    const int gx0=blockIdx.x*64, gy0=blockIdx.y*16;
    for(int idx=tid; idx<CI*CO*9; idx+=256){
        int kk,o,ci; float val=w[idx];
        if(MODE<=1){ o=idx/(CI*9); int r=idx%(CI*9); ci=r/9; kk=r%9; }
        else { int gidx=idx/9; ci=gidx/CO; o=gidx%CO; kk=8-(idx%9); }
        sw2[(ci*9+kk)*CO+o]=val;
    }
    if(MODE<=1){ if(tid<CO) sb[tid]=bias[tid]; }
    if(MODE==1){ if(tid<CO){ float s=0.f; for(int oo=0;oo<8;oo++) s+=aux1[oo*16+tid]; s2s[tid]=s; } }
#pragma unroll 1
    for(int i=tid; i<CI*288; i+=256){
        int ci=i/288; int rem=i-ci*288; int r=rem>>4, k=rem&15;
        int gy=gy0+r-1;
        float4 v4=make_float4(0.f,0.f,0.f,0.f);
        if(gy>=0&&gy<128){
            v4=*(const float4*)(in+((size_t)img*CI+ci)*HWPX+(size_t)gy*128+gx0+4*k);
            if(MODE==1){ v4.x=silu_(v4.x); v4.y=silu_(v4.y); v4.z=silu_(v4.z); v4.w=silu_(v4.w); }
        }
        *(float4*)(sin_+(size_t)(ci*18+r)*72+4+4*k)=v4;
    }
#pragma unroll 1
    for(int i=tid; i<CI*36; i+=256){
        int ci=i/36; int rem=i-ci*36; int r=rem>>1, side=rem&1;
        int tc=side?65:0;
        int gy=gy0+r-1, gx=gx0+tc-1;
        float v=0.f;
        if(gy>=0&&gy<128&&gx>=0&&gx<128){
            v=in[((size_t)img*CI+ci)*HWPX+(size_t)gy*128+gx];
            if(MODE==1) v=silu_(v);
        }
        sin_[(size_t)(ci*18+r)*72+tc+3]=v;
    }
    __syncthreads();
    const int r0=ty*4;
    const int xg=gx0+tx;
    float dtb=0.f; if(MODE==3) dtb=aux2[img>>5];
#pragma unroll 1
    for(int ob=0; ob<CO/8; ob++){
        u64 acc2[4][4];   // [o-pair][q], each holds channels (ob*8+2*op, ob*8+2*op+1)
#pragma unroll
        for(int op=0;op<4;op++)
#pragma unroll
            for(int q=0;q<4;q++) acc2[op][q]=0ull;
#pragma unroll 1
        for(int ci=0;ci<CI;ci++){
            const float* tp=sin_+ci*1296;
            u64 vd[6][3];
#pragma unroll
            for(int rr=0;rr<6;rr++)
#pragma unroll
                for(int ss=0;ss<3;ss++) vd[rr][ss]=pack2(tp[(r0+rr)*72+tx+ss+3]);
            const float* wp=sw2 + (ci*9)*CO + ob*8;
#pragma unroll
            for(int op=0;op<4;op++){
                u64 wv[9];
#pragma unroll
                for(int k=0;k<9;k++) wv[k]=*(const u64*)(wp + k*CO + 2*op);
#pragma unroll
                for(int q=0;q<4;q++){
                    u64 a=acc2[op][q];
                    fma2_(a,wv[0],vd[q  ][0]); fma2_(a,wv[1],vd[q  ][1]); fma2_(a,wv[2],vd[q  ][2]);
                    fma2_(a,wv[3],vd[q+1][0]); fma2_(a,wv[4],vd[q+1][1]); fma2_(a,wv[5],vd[q+1][2]);
                    fma2_(a,wv[6],vd[q+2][0]); fma2_(a,wv[7],vd[q+2][1]); fma2_(a,wv[8],vd[q+2][2]);
                    acc2[op][q]=a;
                }
            }
        }
#pragma unroll 1
        for(int op=0;op<4;op++){
#pragma unroll
            for(int q=0;q<4;q++){
                int y=gy0+r0+q;
                float a0,a1; unpack2(acc2[op][q],a0,a1);
#pragma unroll
                for(int h=0;h<2;h++){
                    int o=ob*8+2*op+h;
                    float a=h?a1:a0;
                    size_t oi=((size_t)img*CO+o)*HWPX+(size_t)y*128+xg;
                    if(MODE==0) out[oi]=a+sb[o];
                    else if(MODE==1){ float z2=a+sb[o]; out[oi]=s2s[o]*silup_(z2); }
                    else if(MODE==2){ out[oi]=a*silup_(aux1[((size_t)img*16+o)*HWPX+(size_t)y*128+xg]); }
                    else out[oi]=aux1[((size_t)img*8+o)*HWPX+(size_t)y*128+xg]+dtb*a;
                }
            }
        }
    }
}

__global__ void k_omega(const float* w1,const float* b1,const float* w2,const float* b2){
    int iy=threadIdx.x, ix=blockIdx.x;
    float ky=(iy<64?(float)iy:(float)(iy-128))*(1.f/128.f), kx=(float)ix*(1.f/128.f);
    float acc[8];
#pragma unroll
    for(int c=0;c<8;c++) acc[c]=0.f;
    for(int h=0;h<64;h++){
        float hid=silu_(fmaf(ky,w1[h],fmaf(kx,w1[64+h],b1[h])));
#pragma unroll
        for(int c=0;c<8;c++) acc[c]=fmaf(hid,w2[h*8+c],acc[c]);
    }
    float kp=sqrtf(ky*ky+kx*kx);
#pragma unroll
    for(int c=0;c<8;c++) d_omega[(iy*WF+ix)*8+c]=acc[c]+b2[c]+kp;
}

__global__ void __launch_bounds__(256) k_fwd2(const float* __restrict__ xt){
    extern __shared__ float2 fs[];
    float2* tw=fs; float2* spec=fs+128; float2* swork=spec+128*67; float2* sZ=swork+16*136;
    int tid=threadIdx.x; build_tw(tw,tid); __syncthreads();
    int g=tid>>4, t=tid&15, IC=blockIdx.x;
    const float* base=xt+(size_t)IC*HWPX;
    for(int pass=0;pass<4;pass++){
        int p=pass*16+g;
        const float* r0=base+(size_t)(2*p)*128; const float* r1=r0+128;
        float2 x[8];
#pragma unroll
        for(int j=0;j<8;j++){ int n=t+16*j; x[j]=make_float2(r0[n],r1[n]); }
        float2 out[16]; fft128<1>(x,out,t,swork+g*136,tw);
        if(t<8){
#pragma unroll
            for(int m=0;m<16;m++) sZ[g*128+t+8*m]=out[m];
        }
        __syncthreads();
        for(int k=t;k<=64;k+=16){
            float2 P=sZ[g*128+k], Q=sZ[g*128+((128-k)&127)];
            spec[(2*p)*67+k]  =make_float2(0.5f*(P.x+Q.x),0.5f*(P.y-Q.y));
            spec[(2*p+1)*67+k]=make_float2(0.5f*(P.y+Q.y),0.5f*(Q.x-P.x));
        }
        __syncthreads();
    }
    for(int pass=0;pass<5;pass++){
        int cr=pass*16+g, c=cr>64?64:cr;
        float2 x[8];
#pragma unroll
        for(int j=0;j<8;j++) x[j]=spec[(t+16*j)*67+c];
        float2 out[16]; fft128<1>(x,out,t,swork+g*136,tw);
        if(t<8 && cr<=64){
#pragma unroll
            for(int m=0;m<16;m++){ float2 v=out[m]; v.x*=(1.f/128.f); v.y*=(1.f/128.f); spec[(t+8*m)*67+c]=v; }
        }
        __syncthreads();
    }
    float2* Sp=d_S+(size_t)IC*NYK;
    for(int i=tid;i<NYK;i+=256){ int y=i/65,k=i-y*65; Sp[i]=spec[y*67+k]; }
}

__global__ void __launch_bounds__(256) k_inv2(float* __restrict__ outp){
    extern __shared__ float2 fs[];
    float2* tw=fs; float2* spec=fs+128; float2* swork=spec+128*67;
    int tid=threadIdx.x; build_tw(tw,tid);
    int g=tid>>4, t=tid&15, IC=blockIdx.x;
    float sc=d_scale[IC>>3]*(1.f/128.f);
    const float2* Sp=d_S2+(size_t)IC*NYK;
    __syncthreads();
    for(int i=tid;i<NYK;i+=256){ int y=i/65,k=i-y*65; float2 v=Sp[i]; v.x*=sc; v.y*=sc; spec[y*67+k]=v; }
    __syncthreads();
    for(int pass=0;pass<5;pass++){
        int cr=pass*16+g, c=cr>64?64:cr;
        float2 x[8];
#pragma unroll
        for(int j=0;j<8;j++) x[j]=spec[(t+16*j)*67+c];
        float2 out[16]; fft128<-1>(x,out,t,swork+g*136,tw);
        if(t<8 && cr<=64){
#pragma unroll
            for(int m=0;m<16;m++) spec[(t+8*m)*67+c]=out[m];
        }
        __syncthreads();
    }
    float* base=outp+(size_t)IC*HWPX;
    for(int pass=0;pass<4;pass++){
        int p=pass*16+g;
        float2 x[8];
#pragma unroll
        for(int j=0;j<8;j++){
            int n=t+16*j; float2 a,b,Z;
            if(n<=64){
                a=spec[(2*p)*67+n]; b=spec[(2*p+1)*67+n];
                if(n==0||n==64){ a.y=0.f; b.y=0.f; }
                Z=make_float2(a.x-b.y,a.y+b.x);
            } else {
                int n2=128-n; a=spec[(2*p)*67+n2]; b=spec[(2*p+1)*67+n2];
                Z=make_float2(a.x+b.y,b.x-a.y);
            }
            x[j]=Z;
        }
        float2 o16[16]; fft128<-1>(x,o16,t,swork+g*136,tw);
        if(t<8){
#pragma unroll
            for(int m=0;m<16;m++){
                int n=t+8*m;
                base[(2*p)*128+n]  =o16[m].x;
                base[(2*p+1)*128+n]=o16[m].y;
            }
        }
        __syncthreads();
    }
}

__global__ void k_project(int buf){
    int e=blockIdx.x*256+threadIdx.x; if(e>=BT*NYK) return;
    int IMG=e/NYK, yk=e%NYK, y=yk/WF, k=yk%WF;
    float gky=(y<64?(float)y:(float)(y-128))*(1.f/128.f), gkx=(float)k*(1.f/128.f);
    float k2=gky*gky+gkx*gkx; if(y==0&&k==0) k2=1.f;
    float2* S=buf?d_S2:d_S;
    float2* U=S+(size_t)(IMG*8+0)*NYK+yk; float2* V=S+(size_t)(IMG*8+1)*NYK+yk;
    float2 u=*U, v=*V;
    float dr=(gky*u.x+gkx*v.x)/k2, di=(gky*u.y+gkx*v.y)/k2;
    *U=make_float2(u.x-gky*dr,u.y-gky*di);
    *V=make_float2(v.x-gkx*dr,v.y-gkx*di);
}

__global__ void k_scan(const float* __restrict__ dt){
    int e=blockIdx.x*256+threadIdx.x; if(e>=4*8*NYK) return;
    int b=e/(8*NYK), r=e%(8*NYK), c=r/NYK, yk=r%NYK;
    float ph=d_omega[yk*8+c]*dt[b];
    float sa,ca; sincosf(ph,&sa,&ca);
    float2 A=make_float2(ca,sa), h=make_float2(0.f,0.f);
    const float2* Xp=d_S+(size_t)(b*32*8+c)*NYK+yk;
    float2* Hp=d_S2+(size_t)(b*32*8+c)*NYK+yk;
#pragma unroll 8
    for(int t=0;t<32;t++){
        float2 X=Xp[(size_t)t*8*NYK];
        h=cadd2(cmul2(A,h),X);
        Hp[(size_t)t*8*NYK]=h;
    }
}

__global__ void __launch_bounds__(1024) k_norm(){
    int IMG=blockIdx.x, tid=threadIdx.x;
    size_t base=(size_t)IMG*8*NYK;
    float s1=0.f,s2=0.f;
    for(int i=tid;i<8*NYK;i+=1024){
        float2 a=d_S[base+i];  s1=fmaf(a.x,a.x,fmaf(a.y,a.y,s1));
        float2 h=d_S2[base+i]; s2=fmaf(h.x,h.x,fmaf(h.y,h.y,s2));
    }
#pragma unroll
    for(int o=16;o;o>>=1){ s1+=__shfl_down_sync(~0u,s1,o); s2+=__shfl_down_sync(~0u,s2,o); }
    __shared__ float r1[32],r2[32];
    if((tid&31)==0){ r1[tid>>5]=s1; r2[tid>>5]=s2; }
    __syncthreads();
    if(tid==0){
        float a=0.f,bb=0.f;
        for(int w=0;w<32;w++){ a+=r1[w]; bb+=r2[w]; }
        d_scale[IMG]=sqrtf(a)/(sqrtf(bb)+1e-6f);
    }
}

extern "C" void kernel_launch(void* const* d_in,const int* in_sizes,int n_in,void* d_out,int out_size){
    const float* x  =(const float*)d_in[0];
    const float* dt =(const float*)d_in[1];
    const float* pw1=(const float*)d_in[2];
    const float* pb1=(const float*)d_in[3];
    const float* pw2=(const float*)d_in[4];
    const float* pb2=(const float*)d_in[5];
    const float* w1 =(const float*)d_in[6];
    const float* b1 =(const float*)d_in[7];
    const float* w2 =(const float*)d_in[8];
    const float* b2 =(const float*)d_in[9];
    const float* w3 =(const float*)d_in[10];

    const int sm0=(8*1296+8*9*16+32)*4;
    const int sm1=(16*1296+16*9*16+32)*4;
    const int sm3=(16*1296+16*9*8+32)*4;
    const int smF=(128+128*67+16*136+16*128)*8;
    const int smI=(128+128*67+16*136)*8;
    cudaFuncSetAttribute(k_conv<8,16,0>,  cudaFuncAttributeMaxDynamicSharedMemorySize, sm0);
    cudaFuncSetAttribute(k_conv<16,16,1>, cudaFuncAttributeMaxDynamicSharedMemorySize, sm1);
    cudaFuncSetAttribute(k_conv<16,16,2>, cudaFuncAttributeMaxDynamicSharedMemorySize, sm1);
    cudaFuncSetAttribute(k_conv<16,8,3>,  cudaFuncAttributeMaxDynamicSharedMemorySize, sm3);
    cudaFuncSetAttribute(k_fwd2, cudaFuncAttributeMaxDynamicSharedMemorySize, smF);
    cudaFuncSetAttribute(k_inv2, cudaFuncAttributeMaxDynamicSharedMemorySize, smI);

    dim3 cg(2,8,128);
    k_omega<<<65,128>>>(pw1,pb1,pw2,pb2);
    k_conv<8,16,0><<<cg,256,sm0>>>(x,   d_z1,w1,b1,nullptr,nullptr);
    k_conv<16,16,1><<<cg,256,sm1>>>(d_z1,d_ga,w2,b2,w3,nullptr);
    k_conv<16,16,2><<<cg,256,sm1>>>(d_ga,d_gb,w2,nullptr,d_z1,nullptr);
    k_conv<16,8,3><<<cg,256,sm3>>>(d_gb,d_Xt,w1,nullptr,x,dt);
    k_fwd2<<<1024,256,smF>>>(d_Xt);
    k_project<<<4160,256>>>(0);
    k_scan<<<1040,256>>>(dt);
    k_project<<<4160,256>>>(1);
    k_norm<<<128,1024>>>();
    k_inv2<<<1024,256,smI>>>((float*)d_out);
}

// round 17
// speedup vs baseline: 1.0382x; 1.0382x over previous
#include <cuda_runtime.h>
#include <math.h>

#define BT 128
#define HWPX 16384
#define WF 65
#define NYK 8320
#define TSTR 1228   // per-buffer stride in floats (18*68+4, 16B-aligned)

__device__ float  d_z1[BT*16*HWPX];
__device__ float  d_ga[BT*16*HWPX];
__device__ float  d_gb[BT*16*HWPX];
__device__ float  d_Xt[BT*8*HWPX];
__device__ float2 d_S [1024*NYK];
__device__ float2 d_S2[1024*NYK];
__device__ float  d_omega[NYK*8];
__device__ float  d_scale[BT];

__device__ __forceinline__ float sg_(float z){ return 1.f/(1.f+__expf(-z)); }
__device__ __forceinline__ float silu_(float z){ return z*sg_(z); }
__device__ __forceinline__ float silup_(float z){ float s=sg_(z); return s+z*s*(1.f-s); }
__device__ __forceinline__ float2 cadd2(float2 a,float2 b){ return make_float2(a.x+b.x,a.y+b.y); }
__device__ __forceinline__ float2 csub2(float2 a,float2 b){ return make_float2(a.x-b.x,a.y-b.y); }
__device__ __forceinline__ float2 cmul2(float2 a,float2 b){ return make_float2(fmaf(a.x,b.x,-(a.y*b.y)),fmaf(a.x,b.y,a.y*b.x)); }
template<int S> __device__ __forceinline__ float2 rotmi(float2 a){ return (S>0)?make_float2(a.y,-a.x):make_float2(-a.y,a.x); }

template<int S> __device__ __forceinline__ void dft4(float2&x0,float2&x1,float2&x2,float2&x3){
    float2 t0=cadd2(x0,x2),t1=csub2(x0,x2),t2=cadd2(x1,x3),t3=csub2(x1,x3);
    x0=cadd2(t0,t2); x2=csub2(t0,t2); float2 r=rotmi<S>(t3); x1=cadd2(t1,r); x3=csub2(t1,r);
}
template<int S> __device__ __forceinline__ void dft8(float2 a[8]){
    float2 e0=a[0],e1=a[2],e2=a[4],e3=a[6],o0=a[1],o1=a[3],o2=a[5],o3=a[7];
    dft4<S>(e0,e1,e2,e3); dft4<S>(o0,o1,o2,o3);
    const float c8=0.70710678118654752f; float2 w1o,w3o;
    if(S>0){ w1o=make_float2(c8*(o1.x+o1.y),c8*(o1.y-o1.x)); w3o=make_float2(c8*(o3.y-o3.x),-c8*(o3.x+o3.y)); }
    else   { w1o=make_float2(c8*(o1.x-o1.y),c8*(o1.y+o1.x)); w3o=make_float2(-c8*(o3.x+o3.y),c8*(o3.x-o3.y)); }
    float2 w2o=rotmi<S>(o2);
    a[0]=cadd2(e0,o0); a[4]=csub2(e0,o0); a[1]=cadd2(e1,w1o); a[5]=csub2(e1,w1o);
    a[2]=cadd2(e2,w2o); a[6]=csub2(e2,w2o); a[3]=cadd2(e3,w3o); a[7]=csub2(e3,w3o);
}
template<int S> __device__ __forceinline__ void dft16(float2 b[16]){
    float2 e[8],o[8];
#pragma unroll
    for(int r=0;r<8;r++){ e[r]=b[2*r]; o[r]=b[2*r+1]; }
    dft8<S>(e); dft8<S>(o);
    const float CW[8]={1.f,0.92387953251128674f,0.70710678118654752f,0.38268343236508977f,0.f,-0.38268343236508977f,-0.70710678118654752f,-0.92387953251128674f};
    const float SW[8]={0.f,0.38268343236508977f,0.70710678118654752f,0.92387953251128674f,1.f,0.92387953251128674f,0.70710678118654752f,0.38268343236508977f};
#pragma unroll
    for(int m=0;m<8;m++){
        float2 w=make_float2(CW[m],(S>0)?-SW[m]:SW[m]);
        float2 wo=cmul2(o[m],w); b[m]=cadd2(e[m],wo); b[m+8]=csub2(e[m],wo);
    }
}
template<int S> __device__ __forceinline__ void fft128(float2 x[8],float2 out[16],int t,float2* wbuf,const float2* tw){
    dft8<S>(x);
#pragma unroll
    for(int k=0;k<8;k++){
        float2 v;
        if(k==0) v=x[0];
        else { float2 w=tw[t*k]; if(S<0) w.y=-w.y; v=cmul2(x[k],w); }
        wbuf[k*17+t]=v;
    }
    __syncthreads();
    if(t<8){
        float2 b[16];
#pragma unroll
        for(int m=0;m<16;m++) b[m]=wbuf[t*17+m];
        dft16<S>(b);
#pragma unroll
        for(int m=0;m<16;m++) out[m]=b[m];
    }
}
__device__ __forceinline__ void build_tw(float2* tw,int tid){
    if(tid<128){ float s,c; sincosf(-6.283185307179586477f*(float)tid/128.f,&s,&c); tw[tid]=make_float2(c,s); }
}

// R6-style small tile, DOUBLE-BUFFERED per-ci: load ci+1 while computing ci; 1 barrier/ci.
// Row stride 68, logical col tc stored at tc+3 (core 4..67 float4-aligned, halos at 3 and 68).
// MODE 0: z1=conv1(x)+b1 | 1: s2*silu'(conv2(silu(z1))+b2) | 2: conv2T(ga)*silu'(z1) | 3: x+dt*conv1T(gb)
template<int CI,int CO,int MODE>
__global__ void __launch_bounds__(256) k_conv(const float* __restrict__ in,float* __restrict__ out,
        const float* __restrict__ w,const float* __restrict__ bias,
        const float* __restrict__ aux1,const float* __restrict__ aux2){
    __shared__ float stile[2*TSTR];
    __shared__ float sw[CI*CO*9];
    __shared__ float sb[16];
    __shared__ float s2s[16];
    const int tid=threadIdx.x;
    const int tx=tid&63, ty=tid>>6;
    const int img=blockIdx.z;
    const int gx0=blockIdx.x*64, gy0=blockIdx.y*16;
    for(int idx=tid; idx<CI*CO*9; idx+=256){
        if(MODE<=1){ int o=idx/(CI*9), r=idx%(CI*9), ci=r/9, k=r%9; sw[(ci*CO+o)*9+k]=w[idx]; }
        else { int i=idx/9, k=idx%9; sw[i*9+(8-k)]=w[idx]; }
    }
    if(MODE<=1){ if(tid<CO) sb[tid]=bias[tid]; }
    if(MODE==1){ if(tid<CO){ float s=0.f; for(int oo=0;oo<8;oo++) s+=aux1[oo*16+tid]; s2s[tid]=s; } }

    // tile loader for channel ci into buffer buf (no barrier inside)
    auto load_tile=[&](int ci,int buf){
        float* dst=stile+buf*TSTR;
        const float* ip=in+((size_t)img*CI+ci)*HWPX;
        // core: 288 float4 (18 rows x 16)
        for(int i=tid;i<288;i+=256){
            int r=i>>4, k=i&15;
            int gy=gy0+r-1;
            float4 v4=make_float4(0.f,0.f,0.f,0.f);
            if(gy>=0&&gy<128){
                v4=*(const float4*)(ip+(size_t)gy*128+gx0+4*k);
                if(MODE==1){ v4.x=silu_(v4.x); v4.y=silu_(v4.y); v4.z=silu_(v4.z); v4.w=silu_(v4.w); }
            }
            *(float4*)(dst+r*68+4+4*k)=v4;
        }
        // halo: 36 scalars
        if(tid<36){
            int r=tid>>1, side=tid&1;
            int tc=side?65:0;
            int gy=gy0+r-1, gx=gx0+tc-1;
            float v=0.f;
            if(gy>=0&&gy<128&&gx>=0&&gx<128){
                v=ip[(size_t)gy*128+gx];
                if(MODE==1) v=silu_(v);
            }
            dst[r*68+tc+3]=v;
        }
    };

    float acc[CO][4];
#pragma unroll
    for(int o=0;o<CO;o++)
#pragma unroll
        for(int q=0;q<4;q++) acc[o][q]=0.f;

    load_tile(0,0);
    __syncthreads();
    const int r0=ty*4;
#pragma unroll 1
    for(int ci=0;ci<CI;ci++){
        if(ci+1<CI) load_tile(ci+1,(ci+1)&1);
        const float* tp=stile+(ci&1)*TSTR;
        float v[6][3];
#pragma unroll
        for(int rr=0;rr<6;rr++)
#pragma unroll
            for(int ss=0;ss<3;ss++) v[rr][ss]=tp[(r0+rr)*68+tx+ss+3];
        const float* swci=&sw[ci*CO*9];
#pragma unroll
        for(int o=0;o<CO;o++){
            const float* wo=swci+o*9;
            float w0=wo[0],w1=wo[1],w2=wo[2],w3=wo[3],w4=wo[4],w5=wo[5],w6=wo[6],w7=wo[7],w8=wo[8];
#pragma unroll
            for(int q=0;q<4;q++){
                float a=acc[o][q];
                a=fmaf(w0,v[q][0],a);   a=fmaf(w1,v[q][1],a);   a=fmaf(w2,v[q][2],a);
                a=fmaf(w3,v[q+1][0],a); a=fmaf(w4,v[q+1][1],a); a=fmaf(w5,v[q+1][2],a);
                a=fmaf(w6,v[q+2][0],a); a=fmaf(w7,v[q+2][1],a); a=fmaf(w8,v[q+2][2],a);
                acc[o][q]=a;
            }
        }
        __syncthreads();
    }
    const int xg=gx0+tx;
    float dtb=0.f; if(MODE==3) dtb=aux2[img>>5];
#pragma unroll 1
    for(int o=0;o<CO;o++){
#pragma unroll
        for(int q=0;q<4;q++){
            int y=gy0+r0+q;
            size_t oi=((size_t)img*CO+o)*HWPX+(size_t)y*128+xg;
            float a=acc[o][q];
            if(MODE==0) out[oi]=a+sb[o];
            else if(MODE==1){ float z2=a+sb[o]; out[oi]=s2s[o]*silup_(z2); }
            else if(MODE==2){ out[oi]=a*silup_(aux1[((size_t)img*16+o)*HWPX+(size_t)y*128+xg]); }
            else out[oi]=aux1[((size_t)img*8+o)*HWPX+(size_t)y*128+xg]+dtb*a;
        }
    }
}

__global__ void k_omega(const float* w1,const float* b1,const float* w2,const float* b2){
    int iy=threadIdx.x, ix=blockIdx.x;
    float ky=(iy<64?(float)iy:(float)(iy-128))*(1.f/128.f), kx=(float)ix*(1.f/128.f);
    float acc[8];
#pragma unroll
    for(int c=0;c<8;c++) acc[c]=0.f;
    for(int h=0;h<64;h++){
        float hid=silu_(fmaf(ky,w1[h],fmaf(kx,w1[64+h],b1[h])));
#pragma unroll
        for(int c=0;c<8;c++) acc[c]=fmaf(hid,w2[h*8+c],acc[c]);
    }
    float kp=sqrtf(ky*ky+kx*kx);
#pragma unroll
    for(int c=0;c<8;c++) d_omega[(iy*WF+ix)*8+c]=acc[c]+b2[c]+kp;
}

__global__ void __launch_bounds__(256) k_fwd2(const float* __restrict__ xt){
    extern __shared__ float2 fs[];
    float2* tw=fs; float2* spec=fs+128; float2* swork=spec+128*67; float2* sZ=swork+16*136;
    int tid=threadIdx.x; build_tw(tw,tid); __syncthreads();
    int g=tid>>4, t=tid&15, IC=blockIdx.x;
    const float* base=xt+(size_t)IC*HWPX;
    for(int pass=0;pass<4;pass++){
        int p=pass*16+g;
        const float* r0=base+(size_t)(2*p)*128; const float* r1=r0+128;
        float2 x[8];
#pragma unroll
        for(int j=0;j<8;j++){ int n=t+16*j; x[j]=make_float2(r0[n],r1[n]); }
        float2 out[16]; fft128<1>(x,out,t,swork+g*136,tw);
        if(t<8){
#pragma unroll
            for(int m=0;m<16;m++) sZ[g*128+t+8*m]=out[m];
        }
        __syncthreads();
        for(int k=t;k<=64;k+=16){
            float2 P=sZ[g*128+k], Q=sZ[g*128+((128-k)&127)];
            spec[(2*p)*67+k]  =make_float2(0.5f*(P.x+Q.x),0.5f*(P.y-Q.y));
            spec[(2*p+1)*67+k]=make_float2(0.5f*(P.y+Q.y),0.5f*(Q.x-P.x));
        }
        __syncthreads();
    }
    for(int pass=0;pass<5;pass++){
        int cr=pass*16+g, c=cr>64?64:cr;
        float2 x[8];
#pragma unroll
        for(int j=0;j<8;j++) x[j]=spec[(t+16*j)*67+c];
        float2 out[16]; fft128<1>(x,out,t,swork+g*136,tw);
        if(t<8 && cr<=64){
#pragma unroll
            for(int m=0;m<16;m++){ float2 v=out[m]; v.x*=(1.f/128.f); v.y*=(1.f/128.f); spec[(t+8*m)*67+c]=v; }
        }
        __syncthreads();
    }
    float2* Sp=d_S+(size_t)IC*NYK;
    for(int i=tid;i<NYK;i+=256){ int y=i/65,k=i-y*65; Sp[i]=spec[y*67+k]; }
}

__global__ void __launch_bounds__(256) k_inv2(float* __restrict__ outp){
    extern __shared__ float2 fs[];
    float2* tw=fs; float2* spec=fs+128; float2* swork=spec+128*67;
    int tid=threadIdx.x; build_tw(tw,tid);
    int g=tid>>4, t=tid&15, IC=blockIdx.x;
    float sc=d_scale[IC>>3]*(1.f/128.f);
    const float2* Sp=d_S2+(size_t)IC*NYK;
    __syncthreads();
    for(int i=tid;i<NYK;i+=256){ int y=i/65,k=i-y*65; float2 v=Sp[i]; v.x*=sc; v.y*=sc; spec[y*67+k]=v; }
    __syncthreads();
    for(int pass=0;pass<5;pass++){
        int cr=pass*16+g, c=cr>64?64:cr;
        float2 x[8];
#pragma unroll
        for(int j=0;j<8;j++) x[j]=spec[(t+16*j)*67+c];
        float2 out[16]; fft128<-1>(x,out,t,swork+g*136,tw);
        if(t<8 && cr<=64){
#pragma unroll
            for(int m=0;m<16;m++) spec[(t+8*m)*67+c]=out[m];
        }
        __syncthreads();
    }
    float* base=outp+(size_t)IC*HWPX;
    for(int pass=0;pass<4;pass++){
        int p=pass*16+g;
        float2 x[8];
#pragma unroll
        for(int j=0;j<8;j++){
            int n=t+16*j; float2 a,b,Z;
            if(n<=64){
                a=spec[(2*p)*67+n]; b=spec[(2*p+1)*67+n];
                if(n==0||n==64){ a.y=0.f; b.y=0.f; }
                Z=make_float2(a.x-b.y,a.y+b.x);
            } else {
                int n2=128-n; a=spec[(2*p)*67+n2]; b=spec[(2*p+1)*67+n2];
                Z=make_float2(a.x+b.y,b.x-a.y);
            }
            x[j]=Z;
        }
        float2 o16[16]; fft128<-1>(x,o16,t,swork+g*136,tw);
        if(t<8){
#pragma unroll
            for(int m=0;m<16;m++){
                int n=t+8*m;
                base[(2*p)*128+n]  =o16[m].x;
                base[(2*p+1)*128+n]=o16[m].y;
            }
        }
        __syncthreads();
    }
}

__global__ void k_project(int buf){
    int e=blockIdx.x*256+threadIdx.x; if(e>=BT*NYK) return;
    int IMG=e/NYK, yk=e%NYK, y=yk/WF, k=yk%WF;
    float gky=(y<64?(float)y:(float)(y-128))*(1.f/128.f), gkx=(float)k*(1.f/128.f);
    float k2=gky*gky+gkx*gkx; if(y==0&&k==0) k2=1.f;
    float2* S=buf?d_S2:d_S;
    float2* U=S+(size_t)(IMG*8+0)*NYK+yk; float2* V=S+(size_t)(IMG*8+1)*NYK+yk;
    float2 u=*U, v=*V;
    float dr=(gky*u.x+gkx*v.x)/k2, di=(gky*u.y+gkx*v.y)/k2;
    *U=make_float2(u.x-gky*dr,u.y-gky*di);
    *V=make_float2(v.x-gkx*dr,v.y-gkx*di);
}

__global__ void k_scan(const float* __restrict__ dt){
    int e=blockIdx.x*256+threadIdx.x; if(e>=4*8*NYK) return;
    int b=e/(8*NYK), r=e%(8*NYK), c=r/NYK, yk=r%NYK;
    float ph=d_omega[yk*8+c]*dt[b];
    float sa,ca; sincosf(ph,&sa,&ca);
    float2 A=make_float2(ca,sa), h=make_float2(0.f,0.f);
    const float2* Xp=d_S+(size_t)(b*32*8+c)*NYK+yk;
    float2* Hp=d_S2+(size_t)(b*32*8+c)*NYK+yk;
#pragma unroll 8
    for(int t=0;t<32;t++){
        float2 X=Xp[(size_t)t*8*NYK];
        h=cadd2(cmul2(A,h),X);
        Hp[(size_t)t*8*NYK]=h;
    }
}

__global__ void __launch_bounds__(1024) k_norm(){
    int IMG=blockIdx.x, tid=threadIdx.x;
    size_t base=(size_t)IMG*8*NYK;
    float s1=0.f,s2=0.f;
    for(int i=tid;i<8*NYK;i+=1024){
        float2 a=d_S[base+i];  s1=fmaf(a.x,a.x,fmaf(a.y,a.y,s1));
        float2 h=d_S2[base+i]; s2=fmaf(h.x,h.x,fmaf(h.y,h.y,s2));
    }
#pragma unroll
    for(int o=16;o;o>>=1){ s1+=__shfl_down_sync(~0u,s1,o); s2+=__shfl_down_sync(~0u,s2,o); }
    __shared__ float r1[32],r2[32];
    if((tid&31)==0){ r1[tid>>5]=s1; r2[tid>>5]=s2; }
    __syncthreads();
    if(tid==0){
        float a=0.f,bb=0.f;
        for(int w=0;w<32;w++){ a+=r1[w]; bb+=r2[w]; }
        d_scale[IMG]=sqrtf(a)/(sqrtf(bb)+1e-6f);
    }
}

extern "C" void kernel_launch(void* const* d_in,const int* in_sizes,int n_in,void* d_out,int out_size){
    const float* x  =(const float*)d_in[0];
    const float* dt =(const float*)d_in[1];
    const float* pw1=(const float*)d_in[2];
    const float* pb1=(const float*)d_in[3];
    const float* pw2=(const float*)d_in[4];
    const float* pb2=(const float*)d_in[5];
    const float* w1 =(const float*)d_in[6];
    const float* b1 =(const float*)d_in[7];
    const float* w2 =(const float*)d_in[8];
    const float* b2 =(const float*)d_in[9];
    const float* w3 =(const float*)d_in[10];

    const int smF=(128+128*67+16*136+16*128)*8;
    const int smI=(128+128*67+16*136)*8;
    cudaFuncSetAttribute(k_fwd2, cudaFuncAttributeMaxDynamicSharedMemorySize, smF);
    cudaFuncSetAttribute(k_inv2, cudaFuncAttributeMaxDynamicSharedMemorySize, smI);

    dim3 cg(2,8,128);
    k_omega<<<65,128>>>(pw1,pb1,pw2,pb2);
    k_conv<8,16,0><<<cg,256>>>(x,   d_z1,w1,b1,nullptr,nullptr);
    k_conv<16,16,1><<<cg,256>>>(d_z1,d_ga,w2,b2,w3,nullptr);
    k_conv<16,16,2><<<cg,256>>>(d_ga,d_gb,w2,nullptr,d_z1,nullptr);
    k_conv<16,8,3><<<cg,256>>>(d_gb,d_Xt,w1,nullptr,x,dt);
    k_fwd2<<<1024,256,smF>>>(d_Xt);
    k_project<<<4160,256>>>(0);
    k_scan<<<1040,256>>>(dt);
    k_project<<<4160,256>>>(1);
    k_norm<<<128,1024>>>();
    k_inv2<<<1024,256,smI>>>((float*)d_out);
}